// round 5
// baseline (speedup 1.0000x reference)
#include <cuda_runtime.h>
#include <cuda_bf16.h>

#define NBAT 2
#define NH 8
#define SEQ 2048
#define DMODEL 1024
#define HD 128
#define TOPK 32
#define NROWS (NBAT*NH*SEQ)
#define L2E 1.4426950408889634f

__device__ int   g_topk[NROWS * TOPK];
__device__ float g_m[NROWS];
__device__ float g_z[NROWS];

__device__ __forceinline__ unsigned okey(float f){
  unsigned u = __float_as_uint(f);
  return u ^ ((unsigned)((int)u >> 31) | 0x80000000u);
}
__device__ __forceinline__ float ex2a(float x){
  float r; asm("ex2.approx.f32 %0, %1;" : "=f"(r) : "f"(x)); return r;
}
__device__ __forceinline__ unsigned long long pk2(float a, float b){
  unsigned long long r; asm("mov.b64 %0, {%1, %2};" : "=l"(r) : "f"(a), "f"(b)); return r;
}
__device__ __forceinline__ void fma2(unsigned long long &c, unsigned long long a, unsigned long long b){
  asm("fma.rn.f32x2 %0, %1, %2, %3;" : "=l"(c) : "l"(a), "l"(b), "l"(c));
}
__device__ __forceinline__ float2 up2(unsigned long long v){
  float2 f; asm("mov.b64 {%0, %1}, %2;" : "=f"(f.x), "=f"(f.y) : "l"(v)); return f;
}

// ---------------- phase A: exact top-32 indices per row ----------------
__global__ void __launch_bounds__(128) topk_kernel(const float* __restrict__ aw){
  __shared__ unsigned s_key[2048];
  __shared__ unsigned long long s_cand[512];
  __shared__ int s_cnt;
  __shared__ int s_red[4];
  const unsigned K0 = 0xBFCCCCCDu;  // okey(1.6f)
  int row = blockIdx.x;
  const float* p = aw + (size_t)row * SEQ;
  int tid = threadIdx.x;
  unsigned kreg[16];
  int cnt = 0;
  #pragma unroll
  for (int it = 0; it < 4; it++){
    int i4 = tid + it*128;
    float4 vv = ((const float4*)p)[i4];
    unsigned k0 = okey(vv.x), k1 = okey(vv.y), k2 = okey(vv.z), k3 = okey(vv.w);
    s_key[i4*4+0]=k0; s_key[i4*4+1]=k1; s_key[i4*4+2]=k2; s_key[i4*4+3]=k3;
    kreg[it*4+0]=k0; kreg[it*4+1]=k1; kreg[it*4+2]=k2; kreg[it*4+3]=k3;
    cnt += (k0>=K0) + (k1>=K0) + (k2>=K0) + (k3>=K0);
  }
  if (tid == 0) s_cnt = 0;
  int c = cnt;
  #pragma unroll
  for (int off=16; off; off>>=1) c += __shfl_xor_sync(0xffffffffu, c, off);
  if ((tid & 31) == 0) s_red[tid>>5] = c;
  __syncthreads();
  int ncand = s_red[0]+s_red[1]+s_red[2]+s_red[3];
  bool normal = (ncand >= TOPK && ncand <= 512);
  if (normal){
    #pragma unroll
    for (int it = 0; it < 4; it++){
      int i4 = tid + it*128;
      #pragma unroll
      for (int j = 0; j < 4; j++){
        unsigned key = kreg[it*4+j];
        if (key >= K0){
          int pos = atomicAdd(&s_cnt, 1);
          s_cand[pos] = ((unsigned long long)key << 32) | (unsigned)(2047 - (i4*4+j));
        }
      }
    }
  }
  __syncthreads();
  if (tid < 32){
    unsigned long long prev = ~0ULL;
    int lim = normal ? ncand : SEQ;
    for (int it = 0; it < TOPK; it++){
      unsigned long long best = 0ULL;
      for (int pi = tid; pi < lim; pi += 32){
        unsigned long long cd = normal ? s_cand[pi]
          : (((unsigned long long)s_key[pi] << 32) | (unsigned)(2047 - pi));
        if (cd < prev && cd > best) best = cd;
      }
      #pragma unroll
      for (int off = 16; off; off >>= 1){
        unsigned long long ob = __shfl_xor_sync(0xffffffffu, best, off);
        if (ob > best) best = ob;
      }
      if (tid == 0) g_topk[(size_t)row*TOPK + it] = 2047 - (int)(unsigned)best;
      prev = best;
    }
  }
}

// ---------------- phase B: QK^T + online softmax (m, Z) ----------------
__global__ void __launch_bounds__(256) qk_kernel(const float* __restrict__ q, const float* __restrict__ k){
  extern __shared__ float sm[];
  float* Qs = sm;               // [128][132]
  float* Ks = sm + 128*132;     // [128 dd][66]
  int qt = blockIdx.x, bh = blockIdx.y;
  int b = bh >> 3, h = bh & 7;
  const float* qb = q + ((size_t)b*SEQ + (size_t)qt*128)*DMODEL + h*HD;
  const float* kb = k + (size_t)b*SEQ*DMODEL + h*HD;
  int tid = threadIdx.x;
  int tx = tid & 15, ty = tid >> 4;
  #pragma unroll
  for (int it = 0; it < 16; it++){
    int idx = tid + it*256;
    int r = idx >> 5, d4 = idx & 31;
    float4 vv = *(const float4*)(qb + (size_t)r*DMODEL + d4*4);
    *(float4*)(Qs + r*132 + d4*4) = vv;
  }
  float m[8], Z[8];
  #pragma unroll
  for (int r = 0; r < 8; r++){ m[r] = -1e30f; Z[r] = 0.f; }
  for (int ch = 0; ch < 32; ch++){
    __syncthreads();
    #pragma unroll
    for (int it = 0; it < 8; it++){
      int idx = tid + it*256;
      int r = idx >> 5, d4 = idx & 31;
      float4 vv = *(const float4*)(kb + (size_t)(ch*64 + r)*DMODEL + d4*4);
      Ks[(d4*4+0)*66 + r] = vv.x;
      Ks[(d4*4+1)*66 + r] = vv.y;
      Ks[(d4*4+2)*66 + r] = vv.z;
      Ks[(d4*4+3)*66 + r] = vv.w;
    }
    __syncthreads();
    unsigned long long acc[8][2];
    #pragma unroll
    for (int r = 0; r < 8; r++){ acc[r][0] = 0ULL; acc[r][1] = 0ULL; }
    #pragma unroll 8
    for (int dd = 0; dd < 128; dd++){
      unsigned long long B0 = *(const unsigned long long*)(Ks + dd*66 + tx*4);
      unsigned long long B1 = *(const unsigned long long*)(Ks + dd*66 + tx*4 + 2);
      #pragma unroll
      for (int r = 0; r < 8; r++){
        float qv = Qs[(ty*8+r)*132 + dd];
        unsigned long long A = pk2(qv, qv);
        fma2(acc[r][0], A, B0);
        fma2(acc[r][1], A, B1);
      }
    }
    #pragma unroll
    for (int r = 0; r < 8; r++){
      float2 s01 = up2(acc[r][0]);
      float2 s23 = up2(acc[r][1]);
      float mt = fmaxf(fmaxf(s01.x, s01.y), fmaxf(s23.x, s23.y));
      #pragma unroll
      for (int off = 8; off; off >>= 1) mt = fmaxf(mt, __shfl_xor_sync(0xffffffffu, mt, off));
      float mn = fmaxf(m[r], mt);
      float ls = ex2a((s01.x-mn)*L2E) + ex2a((s01.y-mn)*L2E)
               + ex2a((s23.x-mn)*L2E) + ex2a((s23.y-mn)*L2E);
      #pragma unroll
      for (int off = 8; off; off >>= 1) ls += __shfl_xor_sync(0xffffffffu, ls, off);
      Z[r] = Z[r]*ex2a((m[r]-mn)*L2E) + ls;
      m[r] = mn;
    }
  }
  if (tx == 0){
    size_t rb = (size_t)bh*SEQ + (size_t)qt*128 + ty*8;
    #pragma unroll
    for (int r = 0; r < 8; r++){ g_m[rb+r] = m[r]; g_z[rb+r] = Z[r]; }
  }
}

// ---------------- phase C: top-32 weights + PV + fused LayerNorm ----------------
__global__ void __launch_bounds__(256) out_kernel(const float* __restrict__ q, const float* __restrict__ k,
    const float* __restrict__ v, const float* __restrict__ gamma, const float* __restrict__ beta,
    float* __restrict__ out){
  __shared__ float q_sh[1024];
  __shared__ float o_sh[1024];
  __shared__ float red[16];
  int blk = blockIdx.x;
  int b = blk >> 11, s = blk & 2047;
  int tid = threadIdx.x;
  int h = tid >> 5, lane = tid & 31;
  size_t tok = ((size_t)b*SEQ + s)*DMODEL;
  *(float4*)(q_sh + tid*4) = *(const float4*)(q + tok + tid*4);
  __syncthreads();
  size_t rbh = ((size_t)(b*NH + h))*SEQ + s;
  float mrow = g_m[rbh], zrow = g_z[rbh];
  int kidx = g_topk[rbh*TOPK + lane];
  const float* kb = k + (size_t)b*SEQ*DMODEL + h*HD;
  const float* vb = v + (size_t)b*SEQ*DMODEL + h*HD;
  const float* krow = kb + (size_t)kidx*DMODEL;
  float acc = 0.f;
  #pragma unroll 8
  for (int d4 = 0; d4 < 32; d4++){
    float4 kk = *(const float4*)(krow + d4*4);
    float4 qq = *(const float4*)(q_sh + h*HD + d4*4);
    acc = fmaf(qq.x, kk.x, acc); acc = fmaf(qq.y, kk.y, acc);
    acc = fmaf(qq.z, kk.z, acc); acc = fmaf(qq.w, kk.w, acc);
  }
  float w = ex2a((acc - mrow)*L2E);
  float wsum = w;
  #pragma unroll
  for (int off = 16; off; off >>= 1) wsum += __shfl_xor_sync(0xffffffffu, wsum, off);
  float coef = w / (wsum + 1e-5f*zrow);
  float o0=0.f,o1=0.f,o2=0.f,o3=0.f;
  #pragma unroll 4
  for (int j = 0; j < TOPK; j++){
    int kj = __shfl_sync(0xffffffffu, kidx, j);
    float cj = __shfl_sync(0xffffffffu, coef, j);
    float4 vv = *(const float4*)(vb + (size_t)kj*DMODEL + lane*4);
    o0 = fmaf(cj, vv.x, o0); o1 = fmaf(cj, vv.y, o1);
    o2 = fmaf(cj, vv.z, o2); o3 = fmaf(cj, vv.w, o3);
  }
  *(float4*)(o_sh + h*HD + lane*4) = make_float4(o0,o1,o2,o3);
  __syncthreads();
  float4 x = *(float4*)(o_sh + tid*4);
  float sum = x.x + x.y + x.z + x.w;
  float sq  = fmaf(x.x,x.x, fmaf(x.y,x.y, fmaf(x.z,x.z, x.w*x.w)));
  #pragma unroll
  for (int off = 16; off; off >>= 1){
    sum += __shfl_xor_sync(0xffffffffu, sum, off);
    sq  += __shfl_xor_sync(0xffffffffu, sq , off);
  }
  if (lane == 0){ red[h] = sum; red[8+h] = sq; }
  __syncthreads();
  if (tid < 8){
    float a = red[tid];
    #pragma unroll
    for (int off = 4; off; off >>= 1) a += __shfl_xor_sync(0xffu, a, off);
    red[tid] = a;
  } else if (tid >= 32 && tid < 40){
    float a = red[8 + (tid-32)];
    #pragma unroll
    for (int off = 4; off; off >>= 1) a += __shfl_xor_sync(0xff00000000ULL ? 0xffu : 0xffu, a, off);
    red[8 + (tid-32)] = a;
  }
  __syncthreads();
  float tsum = red[0], tsq = red[8];
  float mu = tsum * (1.0f/1024.0f);
  float var = tsq * (1.0f/1024.0f) - mu*mu;
  float rstd = rsqrtf(var + 1e-5f);
  float4 g4 = *(const float4*)(gamma + tid*4);
  float4 b4 = *(const float4*)(beta  + tid*4);
  float4 o;
  o.x = (x.x - mu)*rstd*g4.x + b4.x;
  o.y = (x.y - mu)*rstd*g4.y + b4.y;
  o.z = (x.z - mu)*rstd*g4.z + b4.z;
  o.w = (x.w - mu)*rstd*g4.w + b4.w;
  *(float4*)(out + tok + tid*4) = o;
}

extern "C" void kernel_launch(void* const* d_in, const int* in_sizes, int n_in,
                              void* d_out, int out_size){
  const float* q  = (const float*)d_in[0];
  const float* k  = (const float*)d_in[1];
  const float* v  = (const float*)d_in[2];
  const float* aw = (const float*)d_in[3];
  const float* gamma = (const float*)d_in[4];
  const float* beta  = (const float*)d_in[5];
  float* out = (float*)d_out;
  (void)in_sizes; (void)n_in; (void)out_size;

  static bool attr_done = false;
  if (!attr_done){
    cudaFuncSetAttribute(qk_kernel, cudaFuncAttributeMaxDynamicSharedMemorySize, 101376);
    attr_done = true;
  }
  topk_kernel<<<NROWS, 128>>>(aw);
  qk_kernel<<<dim3(16, NBAT*NH), 256, 101376>>>(q, k);
  out_kernel<<<NBAT*SEQ, 256>>>(q, k, v, gamma, beta, out);
}

// round 7
// speedup vs baseline: 1.7337x; 1.7337x over previous
#include <cuda_runtime.h>
#include <cuda_bf16.h>

#define NBAT 2
#define NH 8
#define SEQ 2048
#define DMODEL 1024
#define HD 128
#define TOPK 32
#define NROWS (NBAT*NH*SEQ)
#define L2E 1.4426950408889634f

#define QT 64
#define KSPLIT 2
#define KCH 64
#define NCH ((SEQ/KSPLIT)/KCH)          /* 16 */
#define NITEMS ((SEQ/QT)*(NBAT*NH)*KSPLIT) /* 1024 */
#define QKBLOCKS 304
#define QK_SMEM ((QT*HD + 2*KCH*HD)*4)  /* 98304 */

__device__ int      g_topk[NROWS*TOPK];
__device__ float    g_m[KSPLIT*NROWS];
__device__ float    g_z[KSPLIT*NROWS];
__device__ unsigned g_wq;

__device__ __forceinline__ unsigned okey(float f){
  unsigned u = __float_as_uint(f);
  return u ^ ((unsigned)((int)u >> 31) | 0x80000000u);
}
__device__ __forceinline__ float ex2a(float x){
  float r; asm("ex2.approx.f32 %0, %1;" : "=f"(r) : "f"(x)); return r;
}
__device__ __forceinline__ void fma2(unsigned long long &c, unsigned long long a, unsigned long long b){
  asm("fma.rn.f32x2 %0, %1, %2, %3;" : "=l"(c) : "l"(a), "l"(b), "l"(c));
}
__device__ __forceinline__ float2 up2(unsigned long long v){
  float2 f; asm("mov.b64 {%0, %1}, %2;" : "=f"(f.x), "=f"(f.y) : "l"(v)); return f;
}
__device__ __forceinline__ void cpa16(unsigned dst, const void* src){
  asm volatile("cp.async.ca.shared.global [%0], [%1], 16;\n" :: "r"(dst), "l"(src));
}
__device__ __forceinline__ void cpa_commit(){ asm volatile("cp.async.commit_group;\n"); }
__device__ __forceinline__ void cpa_wait1(){ asm volatile("cp.async.wait_group 1;\n" ::: "memory"); }
__device__ __forceinline__ void cpa_wait0(){ asm volatile("cp.async.wait_group 0;\n" ::: "memory"); }

// ---------------- phase A: exact top-32 indices per row ----------------
__global__ void __launch_bounds__(128) topk_kernel(const float* __restrict__ aw){
  __shared__ unsigned long long s_cand[512];
  __shared__ int s_cnt;
  int row = blockIdx.x;
  const float* p = aw + (size_t)row * SEQ;
  int tid = threadIdx.x;
  if (tid == 0) s_cnt = 0;
  __syncthreads();
  #pragma unroll
  for (int it = 0; it < 4; it++){
    int i4 = tid + it*128;
    float4 vv = ((const float4*)p)[i4];
    float xs[4] = {vv.x, vv.y, vv.z, vv.w};
    #pragma unroll
    for (int j = 0; j < 4; j++){
      if (xs[j] > 1.6f){
        int pos = atomicAdd(&s_cnt, 1);
        if (pos < 512)
          s_cand[pos] = ((unsigned long long)__float_as_uint(xs[j]) << 32)
                      | (unsigned)(2047 - (i4*4+j));
      }
    }
  }
  __syncthreads();
  int ncand = s_cnt;
  bool normal = (ncand >= TOPK && ncand <= 512);
  if (tid < 32){
    unsigned long long prev = ~0ULL;
    int lim = normal ? ncand : SEQ;
    for (int it = 0; it < TOPK; it++){
      unsigned long long best = 0ULL;
      for (int pi = tid; pi < lim; pi += 32){
        unsigned long long cd = normal ? s_cand[pi]
          : (((unsigned long long)okey(p[pi]) << 32) | (unsigned)(2047 - pi));
        if (cd < prev && cd > best) best = cd;
      }
      #pragma unroll
      for (int off = 16; off; off >>= 1){
        unsigned long long ob = __shfl_xor_sync(0xffffffffu, best, off);
        if (ob > best) best = ob;
      }
      if (tid == 0) g_topk[(size_t)row*TOPK + it] = 2047 - (int)(unsigned)best;
      prev = best;
    }
  }
}

// ---------------- phase B: QK^T + online softmax (m, Z), persistent ----------------
__global__ void __launch_bounds__(256, 2) qk_kernel(const float* __restrict__ q, const float* __restrict__ k){
  extern __shared__ float sm[];
  float* Qs  = sm;                 // [64][128] swizzled
  float* Ks0 = sm + QT*HD;         // [2][64][128] swizzled
  __shared__ unsigned s_item;
  int tid = threadIdx.x;
  int tx = tid & 15, ty = tid >> 4;
  unsigned smem_base = (unsigned)__cvta_generic_to_shared(sm);
  int sc_q = ty & 7, sc_k = tx & 7;
  for (;;){
    if (tid == 0) s_item = atomicAdd(&g_wq, 1u);
    __syncthreads();
    unsigned item = s_item;
    if (item >= NITEMS) break;
    int qt = item & 31;
    int bh = (item >> 5) & 15;
    int split = item >> 9;
    int b = bh >> 3, h = bh & 7;
    const float* qb = q + ((size_t)(b*SEQ + qt*QT))*DMODEL + h*HD;
    const float* kb = k + ((size_t)(b*SEQ + split*(SEQ/KSPLIT)))*DMODEL + h*HD;
    #pragma unroll
    for (int it = 0; it < 8; it++){
      int idx = tid + it*256;
      int r = idx >> 5, d4 = idx & 31;
      unsigned dst = smem_base + 4*(r*HD + 4*(d4 ^ ((r>>2)&7)));
      cpa16(dst, qb + (size_t)r*DMODEL + d4*4);
    }
    cpa_commit();
    #pragma unroll
    for (int it = 0; it < 8; it++){
      int idx = tid + it*256;
      int r = idx >> 5, d4 = idx & 31;
      unsigned dst = smem_base + 4*(QT*HD + r*HD + 4*(d4 ^ ((r>>2)&7)));
      cpa16(dst, kb + (size_t)r*DMODEL + d4*4);
    }
    cpa_commit();
    float m0[4], Z0[4];
    #pragma unroll
    for (int i = 0; i < 4; i++){ m0[i] = -1e30f; Z0[i] = 0.f; }
    for (int ch = 0; ch < NCH; ch++){
      const float* Kbuf = Ks0 + (ch & 1)*(KCH*HD);
      if (ch + 1 < NCH){
        const float* kcb = kb + (size_t)(ch+1)*KCH*DMODEL;
        unsigned dbase = smem_base + 4*(QT*HD + ((ch+1)&1)*(KCH*HD));
        #pragma unroll
        for (int it = 0; it < 8; it++){
          int idx = tid + it*256;
          int r = idx >> 5, d4 = idx & 31;
          cpa16(dbase + 4*(r*HD + 4*(d4 ^ ((r>>2)&7))), kcb + (size_t)r*DMODEL + d4*4);
        }
        cpa_commit();
        cpa_wait1();
      } else {
        cpa_wait0();
      }
      __syncthreads();
      unsigned long long acc[4][4];
      #pragma unroll
      for (int i = 0; i < 4; i++)
        #pragma unroll
        for (int j = 0; j < 4; j++) acc[i][j] = 0ULL;
      #pragma unroll 4
      for (int dd4 = 0; dd4 < 32; dd4++){
        int qoff = 4*(dd4 ^ sc_q);
        int koff = 4*(dd4 ^ sc_k);
        ulonglong2 qp[4], kp[4];
        #pragma unroll
        for (int i = 0; i < 4; i++) qp[i] = *(const ulonglong2*)(Qs + (ty*4+i)*HD + qoff);
        #pragma unroll
        for (int j = 0; j < 4; j++) kp[j] = *(const ulonglong2*)(Kbuf + (tx*4+j)*HD + koff);
        #pragma unroll
        for (int i = 0; i < 4; i++)
          #pragma unroll
          for (int j = 0; j < 4; j++){
            fma2(acc[i][j], qp[i].x, kp[j].x);
            fma2(acc[i][j], qp[i].y, kp[j].y);
          }
      }
      #pragma unroll
      for (int i = 0; i < 4; i++){
        float s[4];
        #pragma unroll
        for (int j = 0; j < 4; j++){ float2 f = up2(acc[i][j]); s[j] = f.x + f.y; }
        float mt = fmaxf(fmaxf(s[0], s[1]), fmaxf(s[2], s[3]));
        #pragma unroll
        for (int off = 8; off; off >>= 1) mt = fmaxf(mt, __shfl_xor_sync(0xffffffffu, mt, off));
        float mn = fmaxf(m0[i], mt);
        float ls = ex2a((s[0]-mn)*L2E) + ex2a((s[1]-mn)*L2E)
                 + ex2a((s[2]-mn)*L2E) + ex2a((s[3]-mn)*L2E);
        #pragma unroll
        for (int off = 8; off; off >>= 1) ls += __shfl_xor_sync(0xffffffffu, ls, off);
        Z0[i] = Z0[i]*ex2a((m0[i]-mn)*L2E) + ls;
        m0[i] = mn;
      }
      __syncthreads();
    }
    if (tx == 0){
      size_t rb = (size_t)split*NROWS + (size_t)bh*SEQ + qt*QT + ty*4;
      #pragma unroll
      for (int i = 0; i < 4; i++){ g_m[rb+i] = m0[i]; g_z[rb+i] = Z0[i]; }
    }
    __syncthreads();
  }
}

// ---------------- phase C: top-32 weights + PV + fused LayerNorm ----------------
__global__ void __launch_bounds__(256) out_kernel(const float* __restrict__ q, const float* __restrict__ k,
    const float* __restrict__ v, const float* __restrict__ gamma, const float* __restrict__ beta,
    float* __restrict__ out){
  __shared__ float q_sh[1024];
  __shared__ float o_sh[1024];
  __shared__ float red[18];
  int blk = blockIdx.x;
  int b = blk >> 11, s = blk & 2047;
  int tid = threadIdx.x;
  int h = tid >> 5, lane = tid & 31;
  size_t tok = ((size_t)b*SEQ + s)*DMODEL;
  *(float4*)(q_sh + tid*4) = *(const float4*)(q + tok + tid*4);
  __syncthreads();
  size_t rbh = ((size_t)(b*NH + h))*SEQ + s;
  float m0v = g_m[rbh],        z0v = g_z[rbh];
  float m1v = g_m[NROWS+rbh],  z1v = g_z[NROWS+rbh];
  float mrow = fmaxf(m0v, m1v);
  float zrow = z0v*ex2a((m0v-mrow)*L2E) + z1v*ex2a((m1v-mrow)*L2E);
  int kidx = g_topk[rbh*TOPK + lane];
  const float* kb = k + (size_t)b*SEQ*DMODEL + h*HD;
  const float* vb = v + (size_t)b*SEQ*DMODEL + h*HD;
  const float* krow = kb + (size_t)kidx*DMODEL;
  float acc = 0.f;
  #pragma unroll 8
  for (int d4 = 0; d4 < 32; d4++){
    float4 kk = *(const float4*)(krow + d4*4);
    float4 qq = *(const float4*)(q_sh + h*HD + d4*4);
    acc = fmaf(qq.x, kk.x, acc); acc = fmaf(qq.y, kk.y, acc);
    acc = fmaf(qq.z, kk.z, acc); acc = fmaf(qq.w, kk.w, acc);
  }
  float w = ex2a((acc - mrow)*L2E);
  float wsum = w;
  #pragma unroll
  for (int off = 16; off; off >>= 1) wsum += __shfl_xor_sync(0xffffffffu, wsum, off);
  float coef = w / (wsum + 1e-5f*zrow);
  float o0=0.f, o1=0.f, o2=0.f, o3=0.f;
  #pragma unroll 4
  for (int j = 0; j < TOPK; j++){
    int kj = __shfl_sync(0xffffffffu, kidx, j);
    float cj = __shfl_sync(0xffffffffu, coef, j);
    float4 vv = *(const float4*)(vb + (size_t)kj*DMODEL + lane*4);
    o0 = fmaf(cj, vv.x, o0); o1 = fmaf(cj, vv.y, o1);
    o2 = fmaf(cj, vv.z, o2); o3 = fmaf(cj, vv.w, o3);
  }
  *(float4*)(o_sh + h*HD + lane*4) = make_float4(o0, o1, o2, o3);
  __syncthreads();
  float4 x = *(float4*)(o_sh + tid*4);
  float sum = x.x + x.y + x.z + x.w;
  float sq  = fmaf(x.x,x.x, fmaf(x.y,x.y, fmaf(x.z,x.z, x.w*x.w)));
  #pragma unroll
  for (int off = 16; off; off >>= 1){
    sum += __shfl_xor_sync(0xffffffffu, sum, off);
    sq  += __shfl_xor_sync(0xffffffffu, sq , off);
  }
  if (lane == 0){ red[h] = sum; red[8+h] = sq; }
  __syncthreads();
  if (tid == 0){
    float a = 0.f, c = 0.f;
    #pragma unroll
    for (int t = 0; t < 8; t++){ a += red[t]; c += red[8+t]; }
    red[16] = a; red[17] = c;
  }
  __syncthreads();
  float mu = red[16] * (1.0f/1024.0f);
  float var = red[17] * (1.0f/1024.0f) - mu*mu;
  float rstd = rsqrtf(var + 1e-5f);
  float4 g4 = *(const float4*)(gamma + tid*4);
  float4 b4 = *(const float4*)(beta  + tid*4);
  float4 o;
  o.x = (x.x - mu)*rstd*g4.x + b4.x;
  o.y = (x.y - mu)*rstd*g4.y + b4.y;
  o.z = (x.z - mu)*rstd*g4.z + b4.z;
  o.w = (x.w - mu)*rstd*g4.w + b4.w;
  *(float4*)(out + tok + tid*4) = o;
}

extern "C" void kernel_launch(void* const* d_in, const int* in_sizes, int n_in,
                              void* d_out, int out_size){
  const float* q  = (const float*)d_in[0];
  const float* k  = (const float*)d_in[1];
  const float* v  = (const float*)d_in[2];
  const float* aw = (const float*)d_in[3];
  const float* gamma = (const float*)d_in[4];
  const float* beta  = (const float*)d_in[5];
  float* out = (float*)d_out;
  (void)in_sizes; (void)n_in; (void)out_size;

  static void* wq_addr = nullptr;
  static bool init_done = false;
  if (!init_done){
    cudaFuncSetAttribute(qk_kernel, cudaFuncAttributeMaxDynamicSharedMemorySize, QK_SMEM);
    cudaGetSymbolAddress(&wq_addr, g_wq);
    init_done = true;
  }
  cudaMemsetAsync(wq_addr, 0, 4);
  topk_kernel<<<NROWS, 128>>>(aw);
  qk_kernel<<<QKBLOCKS, 256, QK_SMEM>>>(q, k);
  out_kernel<<<NBAT*SEQ, 256>>>(q, k, v, gamma, beta, out);
}